// round 15
// baseline (speedup 1.0000x reference)
#include <cuda_runtime.h>

#define N 4096
#define T 128                  // tiles of 32 agents
#define NUNITS 8256            // T*(T+1)/2 unordered tile pairs incl diagonal
#define NBLK_A 152             // compile-time grid size (one block per SM)
#define NWARPS_A (NBLK_A * 32) // 4864

#define PED_SPEED  1.34f
#define K_GAIN     2.0f
#define ALPHA      10.66f
#define PED_RADIUS 0.3f
#define PED_MASS   60.0f
#define BETTA      0.71f
#define DT         0.4f
#define COST_A     1.0f
#define COST_B     1.0f
#define COST_E     1.0f
#define EPS        1e-8f

#define LOG2E      1.4426950408889634f
#define LOG2_ALPHA 3.4140815f

// Scratch: g_part[(a*T + o)*32 + lane] = force on agent a*32+lane from tile o.
// Tile a's 128 rows form one contiguous 32 KB chunk. Every slot written exactly
// once per launch (no atomics, deterministic).
__device__ float2 g_part[T * T * 32];
// Monotonic barrier ticket: each launch adds exactly NBLK_A arrivals, so
// target=(old/NBLK_A+1)*NBLK_A is correct on the correctness run and every
// graph replay without any reset (R13-proven).
__device__ unsigned long long g_bar = 0ULL;

__device__ __forceinline__ float fast_rsqrt(float x) {
    float y; asm("rsqrt.approx.ftz.f32 %0, %1;" : "=f"(y) : "f"(x)); return y;
}
__device__ __forceinline__ float fast_ex2(float x) {
    float y; asm("ex2.approx.ftz.f32 %0, %1;" : "=f"(y) : "f"(x)); return y;
}
__device__ __forceinline__ int tri_offset(int a) {   // first unit index of row a
    return 128 * a - (a * (a - 1)) / 2;
}

__global__ __launch_bounds__(1024, 1)
void fused_kernel(const float4* __restrict__ state,
                  const float*  __restrict__ cost_in,
                  const float2* __restrict__ goals,
                  const float*  __restrict__ robot_init_pose,
                  const float4* __restrict__ observed,
                  float4* __restrict__ out,
                  float*  __restrict__ cost_out)
{
    __shared__ float2 spos[N];          // 32 KB (reused after barrier)

    const int tid  = threadIdx.x;
    const int warp = tid >> 5;
    const int lane = tid & 31;

    // ---- Stage positions ----
    #pragma unroll
    for (int k = 0; k < N / 1024; ++k) {
        const int j = tid + k * 1024;
        const float4 s = state[j];
        spos[j] = make_float2(s.x, s.y);
    }
    __syncthreads();

    const float cA  = -(1.0f / BETTA) * LOG2E;
    const float cB2 = (2.0f * PED_RADIUS / BETTA) * LOG2E + LOG2_ALPHA;

    // ================= Phase A (R11/R14-proven codegen) =================
    const int g = warp * NBLK_A + blockIdx.x;

    #pragma unroll
    for (int rep = 0; rep < 2; ++rep) {
        const int u = g + rep * NWARPS_A;
        if (u >= NUNITS) break;

        // Triangular decode: u -> (a, b), a <= b
        int a = (int)(128.5f - sqrtf(fmaf(-2.0f, (float)u, 128.5f * 128.5f)));
        while (tri_offset(a + 1) <= u) ++a;
        while (tri_offset(a) > u) --a;
        const int b = a + (u - tri_offset(a));

        const float2 pa = spos[a * 32 + lane];
        const int bbase = b * 32;

        if (a == b) {
            // Diagonal: one-sided 32x32 (self-step contributes exactly 0)
            float fax = 0.0f, fay = 0.0f;
            #pragma unroll 4
            for (int k = 0; k < 32; ++k) {
                const int m = (lane - k) & 31;
                const float2 pb = spos[bbase + m];
                const float dx = pa.x - pb.x;
                const float dy = pa.y - pb.y;
                const float d2 = fmaf(dx, dx, fmaf(dy, dy, EPS));
                const float rs = fast_rsqrt(d2);
                const float d  = d2 * rs;
                const float e  = fast_ex2(fmaf(d, cA, cB2));
                const float c  = e * rs;
                fax = fmaf(c, dx, fax);
                fay = fmaf(c, dy, fay);
            }
            g_part[(a * T + b) * 32 + lane] = make_float2(fax, fay);
        } else {
            // Off-diagonal: symmetric. fa per-lane (tile a); gb rotates.
            float fax = 0.0f, fay = 0.0f;
            float gbx = 0.0f, gby = 0.0f;
            const int src = (lane + 31) & 31;   // receive from lane-1
            #pragma unroll 4
            for (int k = 0; k < 32; ++k) {
                const int m = (lane - k) & 31;       // b-agent handled this step
                const float2 pb = spos[bbase + m];
                const float dx = pa.x - pb.x;
                const float dy = pa.y - pb.y;
                const float d2 = fmaf(dx, dx, fmaf(dy, dy, EPS));
                const float rs = fast_rsqrt(d2);
                const float d  = d2 * rs;
                const float e  = fast_ex2(fmaf(d, cA, cB2));
                const float c  = e * rs;
                fax = fmaf(c, dx, fax);
                fay = fmaf(c, dy, fay);
                gbx = fmaf(-c, dx, gbx);             // force on b-agent m
                gby = fmaf(-c, dy, gby);
                gbx = __shfl_sync(0xffffffffu, gbx, src);
                gby = __shfl_sync(0xffffffffu, gby, src);
            }
            // after 32 rotations gb is home: lane l holds agent b*32+l
            g_part[(a * T + b) * 32 + lane] = make_float2(fax, fay);
            g_part[(b * T + a) * 32 + lane] = make_float2(gbx, gby);
        }
    }

    // ================= Device-wide barrier (monotonic ticket) =================
    __threadfence();                   // release g_part stores
    __syncthreads();
    if (tid == 0) {
        const unsigned long long old = atomicAdd(&g_bar, 1ULL);
        const unsigned long long target =
            (old / (unsigned long long)NBLK_A + 1ULL) * (unsigned long long)NBLK_A;
        unsigned long long v;
        do {
            asm volatile("ld.global.acquire.gpu.u64 %0, [%1];"
                         : "=l"(v) : "l"(&g_bar));
        } while (v < target);
        __threadfence();               // order subsequent g_part reads
    }
    __syncthreads();

    // ================= Phase B: block t reduces tile t (L2-hot) ==============
    const int t = blockIdx.x;
    if (t < T) {
        // Reuse spos as scratch.
        float2* const s_red = spos;          // [32 warps][32 agents]
        float2* const s_rob = spos + 1024;   // [128] robot rows

        if (tid < T) s_rob[tid] = g_part[tid * 32];   // part[(0*T+o)*32 + 0]

        // warp w sums rows 4w..4w+3 of tile t's contiguous chunk (coalesced)
        {
            const float2* base = &g_part[(t * T + warp * 4) * 32];
            float fx = 0.0f, fy = 0.0f;
            #pragma unroll
            for (int k = 0; k < 4; ++k) {
                const float2 p = base[k * 32 + lane];
                fx += p.x; fy += p.y;
            }
            s_red[warp * 32 + lane] = make_float2(fx, fy);
        }
        __syncthreads();

        if (warp == 0) {
            const int i = t * 32 + lane;

            // own force: fixed-order sum of the 32 warp partials
            float fx = 0.0f, fy = 0.0f;
            #pragma unroll 8
            for (int w = 0; w < 32; ++w) {
                const float2 p = s_red[w * 32 + lane];
                fx += p.x; fy += p.y;
            }

            // robot force: fixed-order sum of 128 rows (identical on all lanes)
            float Rfx = 0.0f, Rfy = 0.0f;
            #pragma unroll 8
            for (int o = 0; o < T; ++o) { Rfx += s_rob[o].x; Rfy += s_rob[o].y; }

            // robot new pose
            const float4 s0 = state[0];
            const float2 g0 = goals[0];
            float r0x, r0y;
            {
                const float tgx = g0.x - s0.x;
                const float tgy = g0.y - s0.y;
                const float inv_gd = fast_rsqrt(fmaf(tgx, tgx, fmaf(tgy, tgy, EPS)));
                const float Fx = Rfx + K_GAIN * PED_MASS * (PED_SPEED * tgx * inv_gd - s0.z);
                const float Fy = Rfy + K_GAIN * PED_MASS * (PED_SPEED * tgy * inv_gd - s0.w);
                float vnx = fmaf(Fx, DT / PED_MASS, s0.z);
                float vny = fmaf(Fy, DT / PED_MASS, s0.w);
                const float spd = sqrtf(fmaf(vnx, vnx, fmaf(vny, vny, EPS)));
                const float sc = fminf(1.0f, PED_SPEED / spd);
                vnx *= sc; vny *= sc;
                r0x = fmaf(vnx, DT, s0.x);
                r0y = fmaf(vny, DT, s0.y);
            }

            // this agent: attraction + propagation
            const float4 s = state[i];
            const float2 g2 = goals[i];
            const float tgx = g2.x - s.x;
            const float tgy = g2.y - s.y;
            const float inv_gd = fast_rsqrt(fmaf(tgx, tgx, fmaf(tgy, tgy, EPS)));
            const float Fx = fx + K_GAIN * PED_MASS * (PED_SPEED * tgx * inv_gd - s.z);
            const float Fy = fy + K_GAIN * PED_MASS * (PED_SPEED * tgy * inv_gd - s.w);

            float vnx = fmaf(Fx, DT / PED_MASS, s.z);
            float vny = fmaf(Fy, DT / PED_MASS, s.w);
            const float spd = sqrtf(fmaf(vnx, vnx, fmaf(vny, vny, EPS)));
            const float sc = fminf(1.0f, PED_SPEED / spd);
            vnx *= sc; vny *= sc;
            const float pnx = fmaf(vnx, DT, s.x);
            const float pny = fmaf(vny, DT, s.y);

            out[i] = make_float4(pnx, pny, vnx, vny);

            // cost
            const float ripx = robot_init_pose[0];
            const float ripy = robot_init_pose[1];
            const float gvx = g0.x - ripx;
            const float gvy = g0.y - ripy;
            const float gnorm = sqrtf(gvx * gvx + gvy * gvy) + EPS;
            const float pg = ((r0x - ripx) * gvx + (r0y - ripy) * gvy) / gnorm;

            const float ddx = pnx - r0x;
            const float ddy = pny - r0y;
            const float dist = sqrtf(fmaf(ddx, ddx, fmaf(ddy, ddy, EPS)));
            const float blame = COST_B * fast_ex2(-dist * (LOG2E / COST_E));

            const float4 obs = observed[i];
            const float ox = pnx - obs.x;
            const float oy = pny - obs.y;
            const float dev = fmaf(ox, ox, oy * oy);

            cost_out[i] = cost_in[i] + (-COST_A * pg + blame + dev);
        }
    }
}

extern "C" void kernel_launch(void* const* d_in, const int* in_sizes, int n_in,
                              void* d_out, int out_size)
{
    const float4* state    = (const float4*)d_in[0];
    const float*  cost_in  = (const float*) d_in[1];
    const float2* goals    = (const float2*)d_in[2];
    const float*  rip      = (const float*) d_in[3];
    const float4* observed = (const float4*)d_in[4];

    float4* out_state = (float4*)d_out;
    float*  cost_out  = (float*)d_out + (size_t)N * 4;

    // NBLK_A = 152 blocks, 1024 threads, 1 block/SM on GB300 (152 SMs):
    // all blocks co-resident -> spin barrier deadlock-free (validated R13).
    fused_kernel<<<NBLK_A, 1024>>>(state, cost_in, goals, rip, observed,
                                   out_state, cost_out);
}

// round 17
// speedup vs baseline: 1.1210x; 1.1210x over previous
#include <cuda_runtime.h>

#define N 4096
#define T 128                 // tiles of 32 agents
#define NUNITS 8256           // T*(T+1)/2 unordered tile pairs incl diagonal
#define NBLK_A 152
#define NWARPS_A (NBLK_A * 32)   // 4864

#define PED_SPEED  1.34f
#define K_GAIN     2.0f
#define ALPHA      10.66f
#define PED_RADIUS 0.3f
#define PED_MASS   60.0f
#define BETTA      0.71f
#define DT         0.4f
#define COST_A     1.0f
#define COST_B     1.0f
#define COST_E     1.0f
#define EPS        1e-8f

#define LOG2E      1.4426950408889634f
#define LOG2_ALPHA 3.4140815f

// Scratch: g_part[(a*T + o)*32 + lane] = force on agent a*32+lane from tile o.
// Tile a's 128 rows form one contiguous 32 KB chunk. Every slot written
// exactly once per launch (no atomics, deterministic).
__device__ float2 g_part[T * T * 32];

__device__ __forceinline__ float fast_rsqrt(float x) {
    float y; asm("rsqrt.approx.ftz.f32 %0, %1;" : "=f"(y) : "f"(x)); return y;
}
__device__ __forceinline__ float fast_ex2(float x) {
    float y; asm("ex2.approx.ftz.f32 %0, %1;" : "=f"(y) : "f"(x)); return y;
}
__device__ __forceinline__ int tri_offset(int a) {   // first unit index of row a
    return 128 * a - (a * (a - 1)) / 2;
}

// ---------------- Phase A: symmetric pair forces, ALU-free inner loop -------
// sdup[t*64 + j] = position of agent t*32 + (j&31): each tile row duplicated,
// so the rotation index (lane-k)&31 becomes the LINEAR index lane+(32-k) and
// every LDS in the fully-unrolled loop gets a compile-time immediate offset.
extern __shared__ float2 sdup[];   // [T*64] = 64 KB

__global__ __launch_bounds__(1024, 1)
void phaseA_kernel(const float4* __restrict__ state)
{
    const int tid  = threadIdx.x;
    const int warp = tid >> 5;
    const int lane = tid & 31;

    // ---- Stage duplicated tile rows ----
    #pragma unroll
    for (int k = 0; k < (T * 64) / 1024; ++k) {      // 8 iterations
        const int idx  = tid + k * 1024;
        const int tile = idx >> 6;
        const int j    = idx & 63;
        const float4 s = state[tile * 32 + (j & 31)];
        sdup[idx] = make_float2(s.x, s.y);
    }
    __syncthreads();

    const float cA  = -(1.0f / BETTA) * LOG2E;
    const float cB2 = (2.0f * PED_RADIUS / BETTA) * LOG2E + LOG2_ALPHA;

    // Transposed warp id: spreads the 2-unit warps evenly across blocks/SMs.
    const int g = warp * NBLK_A + blockIdx.x;

    #pragma unroll
    for (int rep = 0; rep < 2; ++rep) {
        const int u = g + rep * NWARPS_A;
        if (u >= NUNITS) break;

        // Triangular decode: u -> (a, b), a <= b
        int a = (int)(128.5f - sqrtf(fmaf(-2.0f, (float)u, 128.5f * 128.5f)));
        while (tri_offset(a + 1) <= u) ++a;
        while (tri_offset(a) > u) --a;
        const int b = a + (u - tri_offset(a));

        const float2 pa = sdup[a * 64 + lane];
        // pbase[32-k] == pos of b-agent (lane-k)&31 ; offsets 1..32 are
        // compile-time immediates after full unroll.
        const float2* __restrict__ pbase = &sdup[b * 64 + lane];

        if (a == b) {
            // Diagonal: one-sided 32x32 (self-step contributes exactly 0)
            float fax = 0.0f, fay = 0.0f;
            #pragma unroll
            for (int k = 0; k < 32; ++k) {
                const float2 pb = pbase[32 - k];
                const float dx = pa.x - pb.x;
                const float dy = pa.y - pb.y;
                const float d2 = fmaf(dx, dx, fmaf(dy, dy, EPS));
                const float rs = fast_rsqrt(d2);
                const float d  = d2 * rs;
                const float e  = fast_ex2(fmaf(d, cA, cB2));
                const float c  = e * rs;
                fax = fmaf(c, dx, fax);
                fay = fmaf(c, dy, fay);
            }
            g_part[(a * T + b) * 32 + lane] = make_float2(fax, fay);
        } else {
            // Off-diagonal: symmetric. fa per-lane (tile a); gb rotates with
            // the b-agent it represents (2 SHFL/step).
            float fax = 0.0f, fay = 0.0f;
            float gbx = 0.0f, gby = 0.0f;
            const int src = (lane + 31) & 31;   // receive from lane-1
            #pragma unroll
            for (int k = 0; k < 32; ++k) {
                const float2 pb = pbase[32 - k];     // b-agent (lane-k)&31
                const float dx = pa.x - pb.x;
                const float dy = pa.y - pb.y;
                const float d2 = fmaf(dx, dx, fmaf(dy, dy, EPS));
                const float rs = fast_rsqrt(d2);
                const float d  = d2 * rs;
                const float e  = fast_ex2(fmaf(d, cA, cB2));
                const float c  = e * rs;
                fax = fmaf(c, dx, fax);
                fay = fmaf(c, dy, fay);
                gbx = fmaf(-c, dx, gbx);             // reaction on b-agent
                gby = fmaf(-c, dy, gby);
                gbx = __shfl_sync(0xffffffffu, gbx, src);
                gby = __shfl_sync(0xffffffffu, gby, src);
            }
            // after 32 rotations gb is home: lane l holds agent b*32+l
            g_part[(a * T + b) * 32 + lane] = make_float2(fax, fay);
            g_part[(b * T + a) * 32 + lane] = make_float2(gbx, gby);
        }
    }
}

// ---------------- Phase B: one 1024-thread block per tile ----------------
// Warp w sums rows 4w..4w+3 of tile t's contiguous 32 KB chunk (coalesced,
// L2-hot, 4 independent loads per lane x 32 warps -> high MLP), shared tree,
// epilogue on warp 0.
__global__ __launch_bounds__(1024)
void phaseB_kernel(const float4* __restrict__ state,
                   const float*  __restrict__ cost_in,
                   const float2* __restrict__ goals,
                   const float*  __restrict__ robot_init_pose,
                   const float4* __restrict__ observed,
                   float4* __restrict__ out,
                   float*  __restrict__ cost_out)
{
    __shared__ float2 s_red[32 * 32];  // per-warp partial per agent, 8 KB
    __shared__ float2 s_rob[T];        // robot partial rows

    const int t    = blockIdx.x;       // tile 0..127
    const int tid  = threadIdx.x;
    const int warp = tid >> 5;
    const int lane = tid & 31;

    if (tid < T) s_rob[tid] = g_part[tid * 32];   // part[(0*T+o)*32 + 0]

    {
        const float2* base = &g_part[(t * T + warp * 4) * 32];
        float fx = 0.0f, fy = 0.0f;
        #pragma unroll
        for (int k = 0; k < 4; ++k) {
            const float2 p = base[k * 32 + lane];
            fx += p.x; fy += p.y;
        }
        s_red[warp * 32 + lane] = make_float2(fx, fy);
    }
    __syncthreads();

    if (warp == 0) {
        const int i = t * 32 + lane;

        // own force: fixed-order sum of the 32 warp partials
        float fx = 0.0f, fy = 0.0f;
        #pragma unroll 8
        for (int w = 0; w < 32; ++w) {
            const float2 p = s_red[w * 32 + lane];
            fx += p.x; fy += p.y;
        }

        // robot force: fixed-order sum of 128 rows (identical on all lanes)
        float Rfx = 0.0f, Rfy = 0.0f;
        #pragma unroll 8
        for (int o = 0; o < T; ++o) { Rfx += s_rob[o].x; Rfy += s_rob[o].y; }

        // robot new pose
        const float4 s0 = state[0];
        const float2 g0 = goals[0];
        float r0x, r0y;
        {
            const float tgx = g0.x - s0.x;
            const float tgy = g0.y - s0.y;
            const float inv_gd = fast_rsqrt(fmaf(tgx, tgx, fmaf(tgy, tgy, EPS)));
            const float Fx = Rfx + K_GAIN * PED_MASS * (PED_SPEED * tgx * inv_gd - s0.z);
            const float Fy = Rfy + K_GAIN * PED_MASS * (PED_SPEED * tgy * inv_gd - s0.w);
            float vnx = fmaf(Fx, DT / PED_MASS, s0.z);
            float vny = fmaf(Fy, DT / PED_MASS, s0.w);
            const float spd = sqrtf(fmaf(vnx, vnx, fmaf(vny, vny, EPS)));
            const float sc = fminf(1.0f, PED_SPEED / spd);
            vnx *= sc; vny *= sc;
            r0x = fmaf(vnx, DT, s0.x);
            r0y = fmaf(vny, DT, s0.y);
        }

        // this agent: attraction + propagation
        const float4 s = state[i];
        const float2 g = goals[i];
        const float tgx = g.x - s.x;
        const float tgy = g.y - s.y;
        const float inv_gd = fast_rsqrt(fmaf(tgx, tgx, fmaf(tgy, tgy, EPS)));
        const float Fx = fx + K_GAIN * PED_MASS * (PED_SPEED * tgx * inv_gd - s.z);
        const float Fy = fy + K_GAIN * PED_MASS * (PED_SPEED * tgy * inv_gd - s.w);

        float vnx = fmaf(Fx, DT / PED_MASS, s.z);
        float vny = fmaf(Fy, DT / PED_MASS, s.w);
        const float spd = sqrtf(fmaf(vnx, vnx, fmaf(vny, vny, EPS)));
        const float sc = fminf(1.0f, PED_SPEED / spd);
        vnx *= sc; vny *= sc;
        const float pnx = fmaf(vnx, DT, s.x);
        const float pny = fmaf(vny, DT, s.y);

        out[i] = make_float4(pnx, pny, vnx, vny);

        // cost
        const float ripx = robot_init_pose[0];
        const float ripy = robot_init_pose[1];
        const float gvx = g0.x - ripx;
        const float gvy = g0.y - ripy;
        const float gnorm = sqrtf(gvx * gvx + gvy * gvy) + EPS;
        const float pg = ((r0x - ripx) * gvx + (r0y - ripy) * gvy) / gnorm;

        const float ddx = pnx - r0x;
        const float ddy = pny - r0y;
        const float dist = sqrtf(fmaf(ddx, ddx, fmaf(ddy, ddy, EPS)));
        const float blame = COST_B * fast_ex2(-dist * (LOG2E / COST_E));

        const float4 obs = observed[i];
        const float ox = pnx - obs.x;
        const float oy = pny - obs.y;
        const float dev = fmaf(ox, ox, oy * oy);

        cost_out[i] = cost_in[i] + (-COST_A * pg + blame + dev);
    }
}

extern "C" void kernel_launch(void* const* d_in, const int* in_sizes, int n_in,
                              void* d_out, int out_size)
{
    const float4* state    = (const float4*)d_in[0];
    const float*  cost_in  = (const float*) d_in[1];
    const float2* goals    = (const float2*)d_in[2];
    const float*  rip      = (const float*) d_in[3];
    const float4* observed = (const float4*)d_in[4];

    float4* out_state = (float4*)d_out;
    float*  cost_out  = (float*)d_out + (size_t)N * 4;

    const int shmem = T * 64 * sizeof(float2);   // 64 KB
    cudaFuncSetAttribute(phaseA_kernel,
                         cudaFuncAttributeMaxDynamicSharedMemorySize, shmem);

    phaseA_kernel<<<NBLK_A, 1024, shmem>>>(state);
    phaseB_kernel<<<T, 1024>>>(state, cost_in, goals, rip, observed,
                               out_state, cost_out);
}